// round 15
// baseline (speedup 1.0000x reference)
#include <cuda_runtime.h>
#include <stdint.h>
#include <math.h>

#define BATCH  256
#define NPTS   16384
#define QUADS  4
#define QGROUPS (NPTS / 4 / QUADS)          // 1024 groups of 4 pts per CTA
#define THREADS 256
#define GPT (QGROUPS / THREADS)             // 4 groups per thread
#define SPRED_BYTES (QGROUPS * 3 * 16)      // 48 KB raw pred
#define SMEM_BYTES (SPRED_BYTES + QGROUPS * 4)  // + 4 KB packed mask = 52 KB

// scratch: partial sums, counters, flags, solved transforms
__device__ float g_part[BATCH][QUADS][16];
__device__ unsigned g_cnt[BATCH];   // arrival counter (reset by solver)
__device__ unsigned g_done[BATCH];  // rt-ready flag  (reset by last finisher)
__device__ unsigned g_fin[BATCH];   // finish counter (reset by last finisher)
__device__ float g_rt[BATCH][16];

// ---------------------------------------------------------------------------
__device__ __forceinline__ void cp_async16(uint32_t saddr, const void* gaddr) {
    asm volatile("cp.async.cg.shared.global [%0], [%1], 16;"
                 :: "r"(saddr), "l"(gaddr));
}
#define CP_COMMIT()   asm volatile("cp.async.commit_group;" ::: "memory")
#define CP_WAIT_ALL() asm volatile("cp.async.wait_group 0;" ::: "memory")

// ---------------------------------------------------------------------------
// FP32 3x3 Kabsch solve
// ---------------------------------------------------------------------------
__device__ __forceinline__ float nrsqrt(float s) {
    float n = rsqrtf(s);
    return n * (1.5f - 0.5f * s * n * n);
}

__device__ __forceinline__ void jrotf(float S[3][3], float V[3][3], int p, int q) {
    float apq = S[p][q];
    if (fabsf(apq) < 1e-30f) return;
    float theta = (S[q][q] - S[p][p]) / (2.0f * apq);
    float t = copysignf(1.0f, theta) / (fabsf(theta) + sqrtf(theta * theta + 1.0f));
    float c = nrsqrt(t * t + 1.0f);
    float s = t * c;
    int r = 3 - p - q;
    float Spp = S[p][p], Sqq = S[q][q];
    S[p][p] = Spp - t * apq;
    S[q][q] = Sqq + t * apq;
    S[p][q] = S[q][p] = 0.0f;
    float Srp = S[r][p], Srq = S[r][q];
    S[r][p] = S[p][r] = c * Srp - s * Srq;
    S[r][q] = S[q][r] = s * Srp + c * Srq;
#pragma unroll
    for (int i = 0; i < 3; i++) {
        float vp = V[i][p], vq = V[i][q];
        V[i][p] = c * vp - s * vq;
        V[i][q] = s * vp + c * vq;
    }
}

__device__ void kabsch_solve(const float* sums, float* rt) {
    float W = sums[0];
    float invW = 1.0f / W;
    float Swp[3] = {sums[1], sums[2], sums[3]};
    float Swt[3] = {sums[4], sums[5], sums[6]};

    float A[3][3];
#pragma unroll
    for (int i = 0; i < 3; i++)
#pragma unroll
        for (int j = 0; j < 3; j++)
            A[i][j] = sums[7 + 3 * i + j] - Swt[i] * Swp[j] * invW;

    float S[3][3];
#pragma unroll
    for (int j = 0; j < 3; j++)
#pragma unroll
        for (int k = 0; k < 3; k++)
            S[j][k] = A[0][j] * A[0][k] + A[1][j] * A[1][k] + A[2][j] * A[2][k];

    float V[3][3] = {{1,0,0},{0,1,0},{0,0,1}};
#pragma unroll
    for (int sweep = 0; sweep < 12; sweep++) {
        jrotf(S, V, 0, 1);
        jrotf(S, V, 0, 2);
        jrotf(S, V, 1, 2);
    }

    float d[3] = {S[0][0], S[1][1], S[2][2]};
    int id[3] = {0, 1, 2};
    if (d[id[0]] < d[id[1]]) { int t = id[0]; id[0] = id[1]; id[1] = t; }
    if (d[id[0]] < d[id[2]]) { int t = id[0]; id[0] = id[2]; id[2] = t; }
    if (d[id[1]] < d[id[2]]) { int t = id[1]; id[1] = id[2]; id[2] = t; }

    float v1[3], v2[3], v3[3];
#pragma unroll
    for (int i = 0; i < 3; i++) { v1[i] = V[i][id[0]]; v2[i] = V[i][id[1]]; v3[i] = V[i][id[2]]; }

    float u1[3], u2[3];
#pragma unroll
    for (int i = 0; i < 3; i++) u1[i] = A[i][0]*v1[0] + A[i][1]*v1[1] + A[i][2]*v1[2];
    float n1 = nrsqrt(u1[0]*u1[0] + u1[1]*u1[1] + u1[2]*u1[2] + 1e-37f);
#pragma unroll
    for (int i = 0; i < 3; i++) u1[i] *= n1;
#pragma unroll
    for (int i = 0; i < 3; i++) u2[i] = A[i][0]*v2[0] + A[i][1]*v2[1] + A[i][2]*v2[2];
    float dp = u2[0]*u1[0] + u2[1]*u1[1] + u2[2]*u1[2];
#pragma unroll
    for (int i = 0; i < 3; i++) u2[i] -= dp * u1[i];
    float n2 = nrsqrt(u2[0]*u2[0] + u2[1]*u2[1] + u2[2]*u2[2] + 1e-37f);
#pragma unroll
    for (int i = 0; i < 3; i++) u2[i] *= n2;

    float detraw = v1[0]*(v2[1]*v3[2] - v2[2]*v3[1])
                 - v1[1]*(v2[0]*v3[2] - v2[2]*v3[0])
                 + v1[2]*(v2[0]*v3[1] - v2[1]*v3[0]);
    float detV = (detraw >= 0.0f) ? 1.0f : -1.0f;
    float u3[3] = {
        detV * (u1[1]*u2[2] - u1[2]*u2[1]),
        detV * (u1[2]*u2[0] - u1[0]*u2[2]),
        detV * (u1[0]*u2[1] - u1[1]*u2[0])
    };

#pragma unroll
    for (int i = 0; i < 3; i++)
#pragma unroll
        for (int j = 0; j < 3; j++)
            rt[3*i + j] = u1[i]*v1[j] + u2[i]*v2[j] + u3[i]*v3[j];
#pragma unroll
    for (int j = 0; j < 3; j++) rt[9  + j] = Swp[j] * invW;
#pragma unroll
    for (int i = 0; i < 3; i++) rt[12 + i] = Swt[i] * invW;
}

// ---------------------------------------------------------------------------
// Fused kernel with cp.async staging (register-free SMEM fill — no STS
// scoreboard coupling). 4 sibling CTAs per batch, 256 thr, 52 KB dyn SMEM,
// 4 CTAs/SM. pred is read from global EXACTLY ONCE (cp.async); apply reads
// pred + packed mask from SMEM only. LTS traffic: 128 MB read + 48 MB write.
// SMEM layout (SoA, conflict-free): spred[(it*3+c)*256 + tid] = p4[3*g + c].
// ---------------------------------------------------------------------------
__global__ void __launch_bounds__(THREADS, 4) wra_fused(
    const float* __restrict__ pred,
    const float* __restrict__ truec,
    const float* __restrict__ wts,
    const uint32_t* __restrict__ mask,
    float* __restrict__ out)
{
    extern __shared__ char smem_raw[];
    float4*   spred = reinterpret_cast<float4*>(smem_raw);
    uint32_t* smask = reinterpret_cast<uint32_t*>(smem_raw + SPRED_BYTES);

    const int b = blockIdx.x >> 2;
    const int quad = blockIdx.x & 3;
    const int g0 = quad * QGROUPS;

    const float4* __restrict__ p4 = reinterpret_cast<const float4*>(pred  + (size_t)b * NPTS * 3);
    const float4* __restrict__ t4 = reinterpret_cast<const float4*>(truec + (size_t)b * NPTS * 3);
    const float4* __restrict__ w4 = reinterpret_cast<const float4*>(wts   + (size_t)b * NPTS);
    const uint4* __restrict__ m4  = reinterpret_cast<const uint4*>(mask + (size_t)b * NPTS);

    // -------- Phase 0: fire all pred cp.asyncs (12 x 16B per thread) --------
    const uint32_t sbase = (uint32_t)__cvta_generic_to_shared(spred);
#pragma unroll
    for (int it = 0; it < GPT; it++) {
        const int g = g0 + it * THREADS + threadIdx.x;
#pragma unroll
        for (int c = 0; c < 3; c++)
            cp_async16(sbase + (((it * 3 + c) * THREADS + threadIdx.x) << 4),
                       &p4[3 * g + c]);
    }
    CP_COMMIT();

    float acc[16];
#pragma unroll
    for (int i = 0; i < 16; i++) acc[i] = 0.f;

    CP_WAIT_ALL();   // each thread consumes only slots it copied itself

    // -------- Phase 1: reduce own quarter (pred from SMEM, rest LDG) --------
#pragma unroll
    for (int it = 0; it < GPT; it++) {
        const int gl = it * THREADS + threadIdx.x;
        const int g  = g0 + gl;
        float4 a0 = spred[(it*3+0)*THREADS + threadIdx.x];
        float4 a1 = spred[(it*3+1)*THREADS + threadIdx.x];
        float4 a2 = spred[(it*3+2)*THREADS + threadIdx.x];
        float4 c0 = __ldcs(&t4[3*g+0]), c1 = __ldcs(&t4[3*g+1]), c2 = __ldcs(&t4[3*g+2]);
        float4 wv = __ldcs(&w4[g]);
        uint4  mv = __ldcs(&m4[g]);

        float px[4] = {a0.x, a0.w, a1.z, a2.y};
        float py[4] = {a0.y, a1.x, a1.w, a2.z};
        float pz[4] = {a0.z, a1.y, a2.x, a2.w};
        float tx[4] = {c0.x, c0.w, c1.z, c2.y};
        float ty[4] = {c0.y, c1.x, c1.w, c2.z};
        float tz[4] = {c0.z, c1.y, c2.x, c2.w};
        float ww[4] = {wv.x, wv.y, wv.z, wv.w};
        uint32_t mm[4] = {mv.x, mv.y, mv.z, mv.w};

        uint32_t packed = (mm[0] ? 1u : 0u) | (mm[1] ? 2u : 0u)
                        | (mm[2] ? 4u : 0u) | (mm[3] ? 8u : 0u);
        smask[gl] = packed;

#pragma unroll
        for (int k = 0; k < 4; k++) {
            bool mk = ((packed >> k) & 1u) != 0u;
            float mx = mk ? px[k] : 0.f;
            float my = mk ? py[k] : 0.f;
            float mz = mk ? pz[k] : 0.f;
            float wi = mk ? ww[k] : 0.f;
            float wtx = wi * tx[k], wty = wi * ty[k], wtz = wi * tz[k];
            acc[0]  += wi;
            acc[1]  += wi * mx;
            acc[2]  += wi * my;
            acc[3]  += wi * mz;
            acc[4]  += wtx;
            acc[5]  += wty;
            acc[6]  += wtz;
            acc[7]  += wtx * mx;
            acc[8]  += wtx * my;
            acc[9]  += wtx * mz;
            acc[10] += wty * mx;
            acc[11] += wty * my;
            acc[12] += wty * mz;
            acc[13] += wtz * mx;
            acc[14] += wtz * my;
            acc[15] += wtz * mz;
        }
    }

    // -------- Phase 2: block reduce, spin-sync across siblings, solve -------
#pragma unroll
    for (int i = 0; i < 16; i++) {
#pragma unroll
        for (int o = 16; o > 0; o >>= 1)
            acc[i] += __shfl_down_sync(0xffffffffu, acc[i], o);
    }

    __shared__ float sh[THREADS / 32][16];
    __shared__ float prm[15];
    const int warp = threadIdx.x >> 5, lane = threadIdx.x & 31;
    if (lane == 0) {
#pragma unroll
        for (int i = 0; i < 16; i++) sh[warp][i] = acc[i];
    }
    __syncthreads();
    if (threadIdx.x < 16) {
        float s = 0.f;
#pragma unroll
        for (int w = 0; w < THREADS / 32; w++) s += sh[w][threadIdx.x];
        g_part[b][quad][threadIdx.x] = s;
    }
    __syncthreads();

    if (threadIdx.x == 0) {
        __threadfence();
        unsigned prev = atomicAdd(&g_cnt[b], 1u);
        if (prev == QUADS - 1) {
            __threadfence();
            float sums[16];
#pragma unroll
            for (int i = 0; i < 16; i++) {
                float s = 0.f;
#pragma unroll
                for (int c = 0; c < QUADS; c++) s += g_part[b][c][i];
                sums[i] = s;
            }
            float rt[15];
            kabsch_solve(sums, rt);
#pragma unroll
            for (int i = 0; i < 15; i++) g_rt[b][i] = rt[i];
            g_cnt[b] = 0u;                       // reset for next replay
            __threadfence();                     // publish rt before flag
            atomicExch(&g_done[b], 1u);          // release
        } else {
            while (atomicAdd(&g_done[b], 0u) == 0u) __nanosleep(128);
        }
        __threadfence();                         // acquire rt
    }
    __syncthreads();
    if (threadIdx.x < 15) prm[threadIdx.x] = g_rt[b][threadIdx.x];
    __syncthreads();

    const float r00 = prm[0], r01 = prm[1], r02 = prm[2];
    const float r10 = prm[3], r11 = prm[4], r12 = prm[5];
    const float r20 = prm[6], r21 = prm[7], r22 = prm[8];
    const float pc0 = prm[9], pc1 = prm[10], pc2 = prm[11];
    const float tc0 = prm[12], tc1 = prm[13], tc2 = prm[14];

    // -------- Phase 3: apply own quarter entirely from SMEM -----------------
    float4* __restrict__ o4 = reinterpret_cast<float4*>(out + (size_t)b * NPTS * 3);
#pragma unroll
    for (int it = 0; it < GPT; it++) {
        const int gl = it * THREADS + threadIdx.x;
        const int g  = g0 + gl;
        float4 a0 = spred[(it*3+0)*THREADS + threadIdx.x];
        float4 a1 = spred[(it*3+1)*THREADS + threadIdx.x];
        float4 a2 = spred[(it*3+2)*THREADS + threadIdx.x];
        uint32_t packed = smask[gl];

        float px[4] = {a0.x, a0.w, a1.z, a2.y};
        float py[4] = {a0.y, a1.x, a1.w, a2.z};
        float pz[4] = {a0.z, a1.y, a2.x, a2.w};
        float ox[4], oy[4], oz[4];
#pragma unroll
        for (int k = 0; k < 4; k++) {
            bool mk = ((packed >> k) & 1u) != 0u;
            float cx = (mk ? px[k] : 0.f) - pc0;
            float cy = (mk ? py[k] : 0.f) - pc1;
            float cz = (mk ? pz[k] : 0.f) - pc2;
            ox[k] = cx * r00 + cy * r10 + cz * r20 + tc0;
            oy[k] = cx * r01 + cy * r11 + cz * r21 + tc1;
            oz[k] = cx * r02 + cy * r12 + cz * r22 + tc2;
        }
        float4 o0 = {ox[0], oy[0], oz[0], ox[1]};
        float4 o1 = {oy[1], oz[1], ox[2], oy[2]};
        float4 o2 = {oz[2], ox[3], oy[3], oz[3]};
        __stcs(&o4[3*g+0], o0);
        __stcs(&o4[3*g+1], o1);
        __stcs(&o4[3*g+2], o2);
    }

    // -------- Phase 4: reset flags for next graph replay --------------------
    if (threadIdx.x == 0) {
        __threadfence();
        unsigned prev = atomicAdd(&g_fin[b], 1u);
        if (prev == QUADS - 1) {
            g_done[b] = 0u;
            g_fin[b]  = 0u;
        }
    }
}

// ---------------------------------------------------------------------------
extern "C" void kernel_launch(void* const* d_in, const int* in_sizes, int n_in,
                              void* d_out, int out_size) {
    const float*    pred  = (const float*)d_in[0];
    const float*    truec = (const float*)d_in[1];
    const float*    wts   = (const float*)d_in[2];
    const uint32_t* mask  = (const uint32_t*)d_in[3];
    float* out = (float*)d_out;

    cudaFuncSetAttribute(wra_fused, cudaFuncAttributeMaxDynamicSharedMemorySize, SMEM_BYTES);
    wra_fused<<<BATCH * QUADS, THREADS, SMEM_BYTES>>>(pred, truec, wts, mask, out);
}

// round 16
// speedup vs baseline: 1.1284x; 1.1284x over previous
#include <cuda_runtime.h>
#include <stdint.h>
#include <math.h>

#define BATCH  256
#define NPTS   16384
#define CHUNKS 2
#define GRP_PER_CHUNK (NPTS / 4 / CHUNKS)   // 2048 groups of 4 points
#define RED_THREADS 256
#define RED_ITERS (GRP_PER_CHUNK / RED_THREADS)   // 8

// scratch
__device__ float g_part[BATCH][CHUNKS][16];
__device__ unsigned g_cnt[BATCH];                 // zero-init; reset in-kernel
__device__ float g_rt[BATCH][16];
__device__ uint32_t g_mbits[BATCH][CHUNKS * RED_THREADS];  // packed mask bits, 512KB

// ---------------------------------------------------------------------------
// FP32 3x3 Kabsch solve
// ---------------------------------------------------------------------------
__device__ __forceinline__ float nrsqrt(float s) {
    float n = rsqrtf(s);
    return n * (1.5f - 0.5f * s * n * n);   // one Newton step
}

__device__ __forceinline__ void jrotf(float S[3][3], float V[3][3], int p, int q) {
    float apq = S[p][q];
    if (fabsf(apq) < 1e-30f) return;
    float theta = (S[q][q] - S[p][p]) / (2.0f * apq);
    float t = copysignf(1.0f, theta) / (fabsf(theta) + sqrtf(theta * theta + 1.0f));
    float c = nrsqrt(t * t + 1.0f);
    float s = t * c;
    int r = 3 - p - q;
    float Spp = S[p][p], Sqq = S[q][q];
    S[p][p] = Spp - t * apq;
    S[q][q] = Sqq + t * apq;
    S[p][q] = S[q][p] = 0.0f;
    float Srp = S[r][p], Srq = S[r][q];
    S[r][p] = S[p][r] = c * Srp - s * Srq;
    S[r][q] = S[q][r] = s * Srp + c * Srq;
#pragma unroll
    for (int i = 0; i < 3; i++) {
        float vp = V[i][p], vq = V[i][q];
        V[i][p] = c * vp - s * vq;
        V[i][q] = s * vp + c * vq;
    }
}

__device__ void kabsch_solve(const float* sums, float* rt) {
    float W = sums[0];
    float invW = 1.0f / W;
    float Swp[3] = {sums[1], sums[2], sums[3]};
    float Swt[3] = {sums[4], sums[5], sums[6]};

    float A[3][3];  // cov[i][j] = M[i][j] - Swt_i * Swp_j / W
#pragma unroll
    for (int i = 0; i < 3; i++)
#pragma unroll
        for (int j = 0; j < 3; j++)
            A[i][j] = sums[7 + 3 * i + j] - Swt[i] * Swp[j] * invW;

    float S[3][3];
#pragma unroll
    for (int j = 0; j < 3; j++)
#pragma unroll
        for (int k = 0; k < 3; k++)
            S[j][k] = A[0][j] * A[0][k] + A[1][j] * A[1][k] + A[2][j] * A[2][k];

    float V[3][3] = {{1,0,0},{0,1,0},{0,0,1}};
#pragma unroll
    for (int sweep = 0; sweep < 12; sweep++) {
        jrotf(S, V, 0, 1);
        jrotf(S, V, 0, 2);
        jrotf(S, V, 1, 2);
    }

    float d[3] = {S[0][0], S[1][1], S[2][2]};
    int id[3] = {0, 1, 2};
    if (d[id[0]] < d[id[1]]) { int t = id[0]; id[0] = id[1]; id[1] = t; }
    if (d[id[0]] < d[id[2]]) { int t = id[0]; id[0] = id[2]; id[2] = t; }
    if (d[id[1]] < d[id[2]]) { int t = id[1]; id[1] = id[2]; id[2] = t; }

    float v1[3], v2[3], v3[3];
#pragma unroll
    for (int i = 0; i < 3; i++) { v1[i] = V[i][id[0]]; v2[i] = V[i][id[1]]; v3[i] = V[i][id[2]]; }

    float u1[3], u2[3];
#pragma unroll
    for (int i = 0; i < 3; i++) u1[i] = A[i][0]*v1[0] + A[i][1]*v1[1] + A[i][2]*v1[2];
    float n1 = nrsqrt(u1[0]*u1[0] + u1[1]*u1[1] + u1[2]*u1[2] + 1e-37f);
#pragma unroll
    for (int i = 0; i < 3; i++) u1[i] *= n1;
#pragma unroll
    for (int i = 0; i < 3; i++) u2[i] = A[i][0]*v2[0] + A[i][1]*v2[1] + A[i][2]*v2[2];
    float dp = u2[0]*u1[0] + u2[1]*u1[1] + u2[2]*u1[2];
#pragma unroll
    for (int i = 0; i < 3; i++) u2[i] -= dp * u1[i];
    float n2 = nrsqrt(u2[0]*u2[0] + u2[1]*u2[1] + u2[2]*u2[2] + 1e-37f);
#pragma unroll
    for (int i = 0; i < 3; i++) u2[i] *= n2;

    float detraw = v1[0]*(v2[1]*v3[2] - v2[2]*v3[1])
                 - v1[1]*(v2[0]*v3[2] - v2[2]*v3[0])
                 + v1[2]*(v2[0]*v3[1] - v2[1]*v3[0]);
    float detV = (detraw >= 0.0f) ? 1.0f : -1.0f;
    float u3[3] = {
        detV * (u1[1]*u2[2] - u1[2]*u2[1]),
        detV * (u1[2]*u2[0] - u1[0]*u2[2]),
        detV * (u1[0]*u2[1] - u1[1]*u2[0])
    };

#pragma unroll
    for (int i = 0; i < 3; i++)
#pragma unroll
        for (int j = 0; j < 3; j++)
            rt[3*i + j] = u1[i]*v1[j] + u2[i]*v2[j] + u3[i]*v3[j];
#pragma unroll
    for (int j = 0; j < 3; j++) rt[9  + j] = Swp[j] * invW;
#pragma unroll
    for (int i = 0; i < 3; i++) rt[12 + i] = Swt[i] * invW;
}

// ---------------------------------------------------------------------------
// Kernel 1: moment reduction + packed mask-bit export; per-batch last chunk
// block runs the solve (fence + atomic counter).
// Thread t of chunk c covers groups g = c*2048 + it*256 + t, it = 0..7; its
// 8x4 mask bits pack into one uint32 at g_mbits[b][c*256 + t].
// ---------------------------------------------------------------------------
__global__ void __launch_bounds__(RED_THREADS, 4) wra_reduce(
    const float* __restrict__ pred,
    const float* __restrict__ truec,
    const float* __restrict__ wts,
    const uint32_t* __restrict__ mask)
{
    const int b = blockIdx.y;
    const int chunk = blockIdx.x;
    const float4* __restrict__ p4 = reinterpret_cast<const float4*>(pred  + (size_t)b * NPTS * 3);
    const float4* __restrict__ t4 = reinterpret_cast<const float4*>(truec + (size_t)b * NPTS * 3);
    const float4* __restrict__ w4 = reinterpret_cast<const float4*>(wts   + (size_t)b * NPTS);
    const uint4* __restrict__ m4  = reinterpret_cast<const uint4*>(mask + (size_t)b * NPTS);

    float acc[16];
#pragma unroll
    for (int i = 0; i < 16; i++) acc[i] = 0.f;
    uint32_t mbits = 0u;

    const int g0 = chunk * GRP_PER_CHUNK;
#pragma unroll
    for (int it = 0; it < RED_ITERS; it++) {
        const int g = g0 + it * RED_THREADS + threadIdx.x;
        float4 a0 = __ldg(&p4[3*g+0]), a1 = __ldg(&p4[3*g+1]), a2 = __ldg(&p4[3*g+2]);
        float4 c0 = __ldcs(&t4[3*g+0]), c1 = __ldcs(&t4[3*g+1]), c2 = __ldcs(&t4[3*g+2]);
        float4 wv = __ldcs(&w4[g]);
        uint4  mv = __ldcs(&m4[g]);

        float px[4] = {a0.x, a0.w, a1.z, a2.y};
        float py[4] = {a0.y, a1.x, a1.w, a2.z};
        float pz[4] = {a0.z, a1.y, a2.x, a2.w};
        float tx[4] = {c0.x, c0.w, c1.z, c2.y};
        float ty[4] = {c0.y, c1.x, c1.w, c2.z};
        float tz[4] = {c0.z, c1.y, c2.x, c2.w};
        float ww[4] = {wv.x, wv.y, wv.z, wv.w};
        uint32_t mm[4] = {mv.x, mv.y, mv.z, mv.w};

        uint32_t packed = (mm[0] ? 1u : 0u) | (mm[1] ? 2u : 0u)
                        | (mm[2] ? 4u : 0u) | (mm[3] ? 8u : 0u);
        mbits |= packed << (4 * it);

#pragma unroll
        for (int k = 0; k < 4; k++) {
            float wi = ((packed >> k) & 1u) ? ww[k] : 0.f;
            float wtx = wi * tx[k], wty = wi * ty[k], wtz = wi * tz[k];
            acc[0]  += wi;
            acc[1]  += wi * px[k];
            acc[2]  += wi * py[k];
            acc[3]  += wi * pz[k];
            acc[4]  += wtx;
            acc[5]  += wty;
            acc[6]  += wtz;
            acc[7]  += wtx * px[k];
            acc[8]  += wtx * py[k];
            acc[9]  += wtx * pz[k];
            acc[10] += wty * px[k];
            acc[11] += wty * py[k];
            acc[12] += wty * pz[k];
            acc[13] += wtz * px[k];
            acc[14] += wtz * py[k];
            acc[15] += wtz * pz[k];
        }
    }

    // export packed mask bits (512KB total -> L2-resident for apply)
    g_mbits[b][chunk * RED_THREADS + threadIdx.x] = mbits;

    // warp tree-reduce each accumulator
#pragma unroll
    for (int i = 0; i < 16; i++) {
#pragma unroll
        for (int o = 16; o > 0; o >>= 1)
            acc[i] += __shfl_down_sync(0xffffffffu, acc[i], o);
    }

    __shared__ float sh[RED_THREADS / 32][16];
    const int warp = threadIdx.x >> 5, lane = threadIdx.x & 31;
    if (lane == 0) {
#pragma unroll
        for (int i = 0; i < 16; i++) sh[warp][i] = acc[i];
    }
    __syncthreads();
    if (threadIdx.x < 16) {
        float s = 0.f;
#pragma unroll
        for (int w = 0; w < RED_THREADS / 32; w++) s += sh[w][threadIdx.x];
        g_part[b][chunk][threadIdx.x] = s;
    }
    __syncthreads();

    // last-arriving chunk block of this batch performs the solve
    if (threadIdx.x == 0) {
        __threadfence();                                  // publish g_part
        unsigned prev = atomicAdd(&g_cnt[b], 1u);
        if (prev == CHUNKS - 1) {
            __threadfence();                              // acquire peers' g_part
            float sums[16];
#pragma unroll
            for (int i = 0; i < 16; i++) {
                float s = 0.f;
#pragma unroll
                for (int c = 0; c < CHUNKS; c++) s += g_part[b][c][i];
                sums[i] = s;
            }
            float rt[15];
            kabsch_solve(sums, rt);
#pragma unroll
            for (int i = 0; i < 15; i++) g_rt[b][i] = rt[i];
            g_cnt[b] = 0u;                                // reset for next replay
        }
    }
}

// ---------------------------------------------------------------------------
// Kernel 2: apply  out = ((mask?pred:0) - pc) @ R + tc
// Mask comes from the packed L2-resident bitmask (no 16MB mask re-read).
// ---------------------------------------------------------------------------
#define APPLY_GPT 2
#define APPLY_THREADS 256
#define APPLY_BLKX ((NPTS / 4) / (APPLY_THREADS * APPLY_GPT))   // 8

__global__ void __launch_bounds__(APPLY_THREADS, 4) wra_apply(
    const float* __restrict__ pred,
    float* __restrict__ out)
{
    const int b = BATCH - 1 - blockIdx.y;   // reverse batch order (L2 recency)
    __shared__ float prm[15];
    if (threadIdx.x < 15) prm[threadIdx.x] = g_rt[b][threadIdx.x];
    __syncthreads();
    const float r00 = prm[0], r01 = prm[1], r02 = prm[2];
    const float r10 = prm[3], r11 = prm[4], r12 = prm[5];
    const float r20 = prm[6], r21 = prm[7], r22 = prm[8];
    const float pc0 = prm[9], pc1 = prm[10], pc2 = prm[11];
    const float tc0 = prm[12], tc1 = prm[13], tc2 = prm[14];

    const float4* __restrict__ p4 = reinterpret_cast<const float4*>(pred + (size_t)b * NPTS * 3);
    float4* __restrict__ o4 = reinterpret_cast<float4*>(out + (size_t)b * NPTS * 3);

    const int gbase = blockIdx.x * (APPLY_THREADS * APPLY_GPT) + threadIdx.x;

    // Front-batch loads: 6 x 16B pred + 2 packed-mask words (L2-hot scratch)
    float4 A0[APPLY_GPT], A1[APPLY_GPT], A2[APPLY_GPT];
    uint32_t PK[APPLY_GPT];
#pragma unroll
    for (int j = 0; j < APPLY_GPT; j++) {
        const int g = gbase + j * APPLY_THREADS;
        A0[j] = __ldcs(&p4[3*g+0]);
        A1[j] = __ldcs(&p4[3*g+1]);
        A2[j] = __ldcs(&p4[3*g+2]);
        // group g -> chunk c = g/2048, it = (g%2048)/256, t = g%256
        const int c  = g >> 11;
        const int it = (g >> 8) & 7;
        const int t  = g & 255;
        PK[j] = (g_mbits[b][c * RED_THREADS + t] >> (4 * it)) & 0xFu;
    }

#pragma unroll
    for (int j = 0; j < APPLY_GPT; j++) {
        const int g = gbase + j * APPLY_THREADS;
        float px[4] = {A0[j].x, A0[j].w, A1[j].z, A2[j].y};
        float py[4] = {A0[j].y, A1[j].x, A1[j].w, A2[j].z};
        float pz[4] = {A0[j].z, A1[j].y, A2[j].x, A2[j].w};
        float ox[4], oy[4], oz[4];
#pragma unroll
        for (int k = 0; k < 4; k++) {
            bool mk = ((PK[j] >> k) & 1u) != 0u;
            float cx = (mk ? px[k] : 0.f) - pc0;
            float cy = (mk ? py[k] : 0.f) - pc1;
            float cz = (mk ? pz[k] : 0.f) - pc2;
            ox[k] = cx * r00 + cy * r10 + cz * r20 + tc0;
            oy[k] = cx * r01 + cy * r11 + cz * r21 + tc1;
            oz[k] = cx * r02 + cy * r12 + cz * r22 + tc2;
        }
        float4 o0 = {ox[0], oy[0], oz[0], ox[1]};
        float4 o1 = {oy[1], oz[1], ox[2], oy[2]};
        float4 o2 = {oz[2], ox[3], oy[3], oz[3]};
        __stcs(&o4[3*g+0], o0);
        __stcs(&o4[3*g+1], o1);
        __stcs(&o4[3*g+2], o2);
    }
}

// ---------------------------------------------------------------------------
extern "C" void kernel_launch(void* const* d_in, const int* in_sizes, int n_in,
                              void* d_out, int out_size) {
    const float*    pred  = (const float*)d_in[0];
    const float*    truec = (const float*)d_in[1];
    const float*    wts   = (const float*)d_in[2];
    const uint32_t* mask  = (const uint32_t*)d_in[3];
    float* out = (float*)d_out;

    wra_reduce<<<dim3(CHUNKS, BATCH), RED_THREADS>>>(pred, truec, wts, mask);
    wra_apply<<<dim3(APPLY_BLKX, BATCH), APPLY_THREADS>>>(pred, out);
}

// round 17
// speedup vs baseline: 1.1383x; 1.0088x over previous
#include <cuda_runtime.h>
#include <stdint.h>
#include <math.h>

#define BATCH  256
#define NPTS   16384
#define CHUNKS 2
#define GRP_PER_CHUNK (NPTS / 4 / CHUNKS)   // 2048 groups of 4 points
#define RED_THREADS 256
#define RED_ITERS (GRP_PER_CHUNK / RED_THREADS)   // 8

// scratch
__device__ float g_part[BATCH][CHUNKS][16];
__device__ unsigned g_cnt[BATCH];                 // zero-init; reset in-kernel
__device__ float g_rt[BATCH][16];
__device__ uint32_t g_mbits[BATCH][CHUNKS * RED_THREADS];  // packed mask bits, 512KB

// ---------------------------------------------------------------------------
// FP32 3x3 Kabsch solve
// ---------------------------------------------------------------------------
__device__ __forceinline__ float nrsqrt(float s) {
    float n = rsqrtf(s);
    return n * (1.5f - 0.5f * s * n * n);   // one Newton step
}

__device__ __forceinline__ void jrotf(float S[3][3], float V[3][3], int p, int q) {
    float apq = S[p][q];
    if (fabsf(apq) < 1e-30f) return;
    float theta = (S[q][q] - S[p][p]) / (2.0f * apq);
    float t = copysignf(1.0f, theta) / (fabsf(theta) + sqrtf(theta * theta + 1.0f));
    float c = nrsqrt(t * t + 1.0f);
    float s = t * c;
    int r = 3 - p - q;
    float Spp = S[p][p], Sqq = S[q][q];
    S[p][p] = Spp - t * apq;
    S[q][q] = Sqq + t * apq;
    S[p][q] = S[q][p] = 0.0f;
    float Srp = S[r][p], Srq = S[r][q];
    S[r][p] = S[p][r] = c * Srp - s * Srq;
    S[r][q] = S[q][r] = s * Srp + c * Srq;
#pragma unroll
    for (int i = 0; i < 3; i++) {
        float vp = V[i][p], vq = V[i][q];
        V[i][p] = c * vp - s * vq;
        V[i][q] = s * vp + c * vq;
    }
}

__device__ void kabsch_solve(const float* sums, float* rt) {
    float W = sums[0];
    float invW = 1.0f / W;
    float Swp[3] = {sums[1], sums[2], sums[3]};
    float Swt[3] = {sums[4], sums[5], sums[6]};

    float A[3][3];  // cov[i][j] = M[i][j] - Swt_i * Swp_j / W
#pragma unroll
    for (int i = 0; i < 3; i++)
#pragma unroll
        for (int j = 0; j < 3; j++)
            A[i][j] = sums[7 + 3 * i + j] - Swt[i] * Swp[j] * invW;

    float S[3][3];
#pragma unroll
    for (int j = 0; j < 3; j++)
#pragma unroll
        for (int k = 0; k < 3; k++)
            S[j][k] = A[0][j] * A[0][k] + A[1][j] * A[1][k] + A[2][j] * A[2][k];

    float V[3][3] = {{1,0,0},{0,1,0},{0,0,1}};
#pragma unroll
    for (int sweep = 0; sweep < 12; sweep++) {
        jrotf(S, V, 0, 1);
        jrotf(S, V, 0, 2);
        jrotf(S, V, 1, 2);
    }

    float d[3] = {S[0][0], S[1][1], S[2][2]};
    int id[3] = {0, 1, 2};
    if (d[id[0]] < d[id[1]]) { int t = id[0]; id[0] = id[1]; id[1] = t; }
    if (d[id[0]] < d[id[2]]) { int t = id[0]; id[0] = id[2]; id[2] = t; }
    if (d[id[1]] < d[id[2]]) { int t = id[1]; id[1] = id[2]; id[2] = t; }

    float v1[3], v2[3], v3[3];
#pragma unroll
    for (int i = 0; i < 3; i++) { v1[i] = V[i][id[0]]; v2[i] = V[i][id[1]]; v3[i] = V[i][id[2]]; }

    float u1[3], u2[3];
#pragma unroll
    for (int i = 0; i < 3; i++) u1[i] = A[i][0]*v1[0] + A[i][1]*v1[1] + A[i][2]*v1[2];
    float n1 = nrsqrt(u1[0]*u1[0] + u1[1]*u1[1] + u1[2]*u1[2] + 1e-37f);
#pragma unroll
    for (int i = 0; i < 3; i++) u1[i] *= n1;
#pragma unroll
    for (int i = 0; i < 3; i++) u2[i] = A[i][0]*v2[0] + A[i][1]*v2[1] + A[i][2]*v2[2];
    float dp = u2[0]*u1[0] + u2[1]*u1[1] + u2[2]*u1[2];
#pragma unroll
    for (int i = 0; i < 3; i++) u2[i] -= dp * u1[i];
    float n2 = nrsqrt(u2[0]*u2[0] + u2[1]*u2[1] + u2[2]*u2[2] + 1e-37f);
#pragma unroll
    for (int i = 0; i < 3; i++) u2[i] *= n2;

    float detraw = v1[0]*(v2[1]*v3[2] - v2[2]*v3[1])
                 - v1[1]*(v2[0]*v3[2] - v2[2]*v3[0])
                 + v1[2]*(v2[0]*v3[1] - v2[1]*v3[0]);
    float detV = (detraw >= 0.0f) ? 1.0f : -1.0f;
    float u3[3] = {
        detV * (u1[1]*u2[2] - u1[2]*u2[1]),
        detV * (u1[2]*u2[0] - u1[0]*u2[2]),
        detV * (u1[0]*u2[1] - u1[1]*u2[0])
    };

#pragma unroll
    for (int i = 0; i < 3; i++)
#pragma unroll
        for (int j = 0; j < 3; j++)
            rt[3*i + j] = u1[i]*v1[j] + u2[i]*v2[j] + u3[i]*v3[j];
#pragma unroll
    for (int j = 0; j < 3; j++) rt[9  + j] = Swp[j] * invW;
#pragma unroll
    for (int i = 0; i < 3; i++) rt[12 + i] = Swt[i] * invW;
}

// ---------------------------------------------------------------------------
// Kernel 1: moment reduction (R10 memory policy: __ldg pred+mask so those
// lines stay L2-cached for apply / next replay, __ldcs true+weights) + packed
// mask-bit export; per-batch last chunk block runs the solve.
// ---------------------------------------------------------------------------
__global__ void __launch_bounds__(RED_THREADS, 4) wra_reduce(
    const float* __restrict__ pred,
    const float* __restrict__ truec,
    const float* __restrict__ wts,
    const uint32_t* __restrict__ mask)
{
    const int b = blockIdx.y;
    const int chunk = blockIdx.x;
    const float4* __restrict__ p4 = reinterpret_cast<const float4*>(pred  + (size_t)b * NPTS * 3);
    const float4* __restrict__ t4 = reinterpret_cast<const float4*>(truec + (size_t)b * NPTS * 3);
    const float4* __restrict__ w4 = reinterpret_cast<const float4*>(wts   + (size_t)b * NPTS);
    const uint4* __restrict__ m4  = reinterpret_cast<const uint4*>(mask + (size_t)b * NPTS);

    float acc[16];
#pragma unroll
    for (int i = 0; i < 16; i++) acc[i] = 0.f;
    uint32_t mbits = 0u;

    const int g0 = chunk * GRP_PER_CHUNK;
#pragma unroll
    for (int it = 0; it < RED_ITERS; it++) {
        const int g = g0 + it * RED_THREADS + threadIdx.x;
        float4 a0 = __ldg(&p4[3*g+0]), a1 = __ldg(&p4[3*g+1]), a2 = __ldg(&p4[3*g+2]);
        float4 c0 = __ldcs(&t4[3*g+0]), c1 = __ldcs(&t4[3*g+1]), c2 = __ldcs(&t4[3*g+2]);
        float4 wv = __ldcs(&w4[g]);
        uint4  mv = __ldg(&m4[g]);

        float px[4] = {a0.x, a0.w, a1.z, a2.y};
        float py[4] = {a0.y, a1.x, a1.w, a2.z};
        float pz[4] = {a0.z, a1.y, a2.x, a2.w};
        float tx[4] = {c0.x, c0.w, c1.z, c2.y};
        float ty[4] = {c0.y, c1.x, c1.w, c2.z};
        float tz[4] = {c0.z, c1.y, c2.x, c2.w};
        float ww[4] = {wv.x, wv.y, wv.z, wv.w};
        uint32_t mm[4] = {mv.x, mv.y, mv.z, mv.w};

        uint32_t packed = (mm[0] ? 1u : 0u) | (mm[1] ? 2u : 0u)
                        | (mm[2] ? 4u : 0u) | (mm[3] ? 8u : 0u);
        mbits |= packed << (4 * it);

#pragma unroll
        for (int k = 0; k < 4; k++) {
            float wi = ((packed >> k) & 1u) ? ww[k] : 0.f;
            float wtx = wi * tx[k], wty = wi * ty[k], wtz = wi * tz[k];
            acc[0]  += wi;
            acc[1]  += wi * px[k];
            acc[2]  += wi * py[k];
            acc[3]  += wi * pz[k];
            acc[4]  += wtx;
            acc[5]  += wty;
            acc[6]  += wtz;
            acc[7]  += wtx * px[k];
            acc[8]  += wtx * py[k];
            acc[9]  += wtx * pz[k];
            acc[10] += wty * px[k];
            acc[11] += wty * py[k];
            acc[12] += wty * pz[k];
            acc[13] += wtz * px[k];
            acc[14] += wtz * py[k];
            acc[15] += wtz * pz[k];
        }
    }

    // export packed mask bits (512KB total -> L2-resident for apply)
    g_mbits[b][chunk * RED_THREADS + threadIdx.x] = mbits;

    // warp tree-reduce each accumulator
#pragma unroll
    for (int i = 0; i < 16; i++) {
#pragma unroll
        for (int o = 16; o > 0; o >>= 1)
            acc[i] += __shfl_down_sync(0xffffffffu, acc[i], o);
    }

    __shared__ float sh[RED_THREADS / 32][16];
    const int warp = threadIdx.x >> 5, lane = threadIdx.x & 31;
    if (lane == 0) {
#pragma unroll
        for (int i = 0; i < 16; i++) sh[warp][i] = acc[i];
    }
    __syncthreads();
    if (threadIdx.x < 16) {
        float s = 0.f;
#pragma unroll
        for (int w = 0; w < RED_THREADS / 32; w++) s += sh[w][threadIdx.x];
        g_part[b][chunk][threadIdx.x] = s;
    }
    __syncthreads();

    // last-arriving chunk block of this batch performs the solve
    if (threadIdx.x == 0) {
        __threadfence();                                  // publish g_part
        unsigned prev = atomicAdd(&g_cnt[b], 1u);
        if (prev == CHUNKS - 1) {
            __threadfence();                              // acquire peers' g_part
            float sums[16];
#pragma unroll
            for (int i = 0; i < 16; i++) {
                float s = 0.f;
#pragma unroll
                for (int c = 0; c < CHUNKS; c++) s += g_part[b][c][i];
                sums[i] = s;
            }
            float rt[15];
            kabsch_solve(sums, rt);
#pragma unroll
            for (int i = 0; i < 15; i++) g_rt[b][i] = rt[i];
            g_cnt[b] = 0u;                                // reset for next replay
        }
    }
}

// ---------------------------------------------------------------------------
// Kernel 2: apply  out = ((mask?pred:0) - pc) @ R + tc
// Mask from packed L2-resident bitmask (no 16MB mask re-read). 19.6us in R16.
// ---------------------------------------------------------------------------
#define APPLY_GPT 2
#define APPLY_THREADS 256
#define APPLY_BLKX ((NPTS / 4) / (APPLY_THREADS * APPLY_GPT))   // 8

__global__ void __launch_bounds__(APPLY_THREADS, 4) wra_apply(
    const float* __restrict__ pred,
    float* __restrict__ out)
{
    const int b = BATCH - 1 - blockIdx.y;   // reverse batch order (L2 recency)
    __shared__ float prm[15];
    if (threadIdx.x < 15) prm[threadIdx.x] = g_rt[b][threadIdx.x];
    __syncthreads();
    const float r00 = prm[0], r01 = prm[1], r02 = prm[2];
    const float r10 = prm[3], r11 = prm[4], r12 = prm[5];
    const float r20 = prm[6], r21 = prm[7], r22 = prm[8];
    const float pc0 = prm[9], pc1 = prm[10], pc2 = prm[11];
    const float tc0 = prm[12], tc1 = prm[13], tc2 = prm[14];

    const float4* __restrict__ p4 = reinterpret_cast<const float4*>(pred + (size_t)b * NPTS * 3);
    float4* __restrict__ o4 = reinterpret_cast<float4*>(out + (size_t)b * NPTS * 3);

    const int gbase = blockIdx.x * (APPLY_THREADS * APPLY_GPT) + threadIdx.x;

    // Front-batch loads: 6 x 16B pred + 2 packed-mask words (L2-hot scratch)
    float4 A0[APPLY_GPT], A1[APPLY_GPT], A2[APPLY_GPT];
    uint32_t PK[APPLY_GPT];
#pragma unroll
    for (int j = 0; j < APPLY_GPT; j++) {
        const int g = gbase + j * APPLY_THREADS;
        A0[j] = __ldcs(&p4[3*g+0]);
        A1[j] = __ldcs(&p4[3*g+1]);
        A2[j] = __ldcs(&p4[3*g+2]);
        const int c  = g >> 11;
        const int it = (g >> 8) & 7;
        const int t  = g & 255;
        PK[j] = (g_mbits[b][c * RED_THREADS + t] >> (4 * it)) & 0xFu;
    }

#pragma unroll
    for (int j = 0; j < APPLY_GPT; j++) {
        const int g = gbase + j * APPLY_THREADS;
        float px[4] = {A0[j].x, A0[j].w, A1[j].z, A2[j].y};
        float py[4] = {A0[j].y, A1[j].x, A1[j].w, A2[j].z};
        float pz[4] = {A0[j].z, A1[j].y, A2[j].x, A2[j].w};
        float ox[4], oy[4], oz[4];
#pragma unroll
        for (int k = 0; k < 4; k++) {
            bool mk = ((PK[j] >> k) & 1u) != 0u;
            float cx = (mk ? px[k] : 0.f) - pc0;
            float cy = (mk ? py[k] : 0.f) - pc1;
            float cz = (mk ? pz[k] : 0.f) - pc2;
            ox[k] = cx * r00 + cy * r10 + cz * r20 + tc0;
            oy[k] = cx * r01 + cy * r11 + cz * r21 + tc1;
            oz[k] = cx * r02 + cy * r12 + cz * r22 + tc2;
        }
        float4 o0 = {ox[0], oy[0], oz[0], ox[1]};
        float4 o1 = {oy[1], oz[1], ox[2], oy[2]};
        float4 o2 = {oz[2], ox[3], oy[3], oz[3]};
        __stcs(&o4[3*g+0], o0);
        __stcs(&o4[3*g+1], o1);
        __stcs(&o4[3*g+2], o2);
    }
}

// ---------------------------------------------------------------------------
extern "C" void kernel_launch(void* const* d_in, const int* in_sizes, int n_in,
                              void* d_out, int out_size) {
    const float*    pred  = (const float*)d_in[0];
    const float*    truec = (const float*)d_in[1];
    const float*    wts   = (const float*)d_in[2];
    const uint32_t* mask  = (const uint32_t*)d_in[3];
    float* out = (float*)d_out;

    wra_reduce<<<dim3(CHUNKS, BATCH), RED_THREADS>>>(pred, truec, wts, mask);
    wra_apply<<<dim3(APPLY_BLKX, BATCH), APPLY_THREADS>>>(pred, out);
}